// round 1
// baseline (speedup 1.0000x reference)
#include <cuda_runtime.h>
#include <cstdint>

#define B_    16384
#define S_    17
#define V_    29
#define D_    128
#define NSEG_ 4
#define L_    6
#define NB    4
#define ROWS  (NB * S_)          // 68
#define NT    256
#define EPS_  1e-5f
#define SCP   20                 // padded score row stride

// ---- shared memory layout (in floats) ----
#define OFF_XS   0
#define OFF_QS   (OFF_XS + ROWS * D_)        // 8704
#define OFF_KS   (OFF_QS + ROWS * D_)
#define OFF_VS   (OFF_KS + ROWS * D_)
#define OFF_W    (OFF_VS + ROWS * D_)        // 34816, 16384 floats
#define OFF_SC   (OFF_W + D_ * D_)           // NB*17*SCP = 1360
#define OFF_RED  (OFF_SC + NB * S_ * SCP)    // ROWS*8
#define OFF_ST   (OFF_RED + ROWS * 8)        // ROWS*2
#define OFF_MK   (OFF_ST + ROWS * 2)         // ROWS
#define OFF_SG   (OFF_MK + ROWS)             // ROWS*4
#define OFF_XI   (OFF_SG + ROWS * 4)         // NB*17*32
#define SMEM_FLOATS (OFF_XI + NB * S_ * 32)
#define SMEM_BYTES  (SMEM_FLOATS * 4)        // 223024 B

// ============================================================
// GEMM: dst[ROWS][128] = act( src[ROWS][128] @ Wg[128][128] + bg )
// Lane owns 4 consecutive output columns, warp owns rows {rg, rg+8, ...}.
// Weights staged into smem (wsm) cooperatively.
// ============================================================
template <bool RELU>
__device__ __forceinline__ void do_gemm(
    const float* __restrict__ src, float* __restrict__ dst,
    const float* __restrict__ Wg, const float* __restrict__ bg,
    float* __restrict__ wsm)
{
    const int t = threadIdx.x;
    __syncthreads();   // prior consumers of wsm / producers of src are done
    {
        const float4* w4 = (const float4*)Wg;
        float4* s4 = (float4*)wsm;
#pragma unroll
        for (int i = 0; i < (D_ * D_ / 4) / NT; i++)   // 16 iters
            s4[t + i * NT] = w4[t + i * NT];
    }
    __syncthreads();

    const int c  = (t & 31) << 2;   // columns c..c+3
    const int rg = t >> 5;          // warp id 0..7 -> rows rg + 8*i
    const bool hasE = (rg < (ROWS - 64));   // rows 64..67 -> warps 0..3

    float acc[8][4];
    float ace[4];
    const float4 bb = *(const float4*)&bg[c];
#pragma unroll
    for (int i = 0; i < 8; i++) {
        acc[i][0] = bb.x; acc[i][1] = bb.y; acc[i][2] = bb.z; acc[i][3] = bb.w;
    }
    ace[0] = bb.x; ace[1] = bb.y; ace[2] = bb.z; ace[3] = bb.w;

#pragma unroll 4
    for (int k = 0; k < D_; k++) {
        const float4 w = *(const float4*)&wsm[k * D_ + c];
#pragma unroll
        for (int i = 0; i < 8; i++) {
            const float xv = src[(rg + (i << 3)) * D_ + k];   // warp-broadcast LDS
            acc[i][0] += xv * w.x; acc[i][1] += xv * w.y;
            acc[i][2] += xv * w.z; acc[i][3] += xv * w.w;
        }
        if (hasE) {
            const float xv = src[(rg + 64) * D_ + k];
            ace[0] += xv * w.x; ace[1] += xv * w.y;
            ace[2] += xv * w.z; ace[3] += xv * w.w;
        }
    }

#pragma unroll
    for (int i = 0; i < 8; i++) {
        float4 o = make_float4(acc[i][0], acc[i][1], acc[i][2], acc[i][3]);
        if (RELU) {
            o.x = fmaxf(o.x, 0.f); o.y = fmaxf(o.y, 0.f);
            o.z = fmaxf(o.z, 0.f); o.w = fmaxf(o.w, 0.f);
        }
        *(float4*)&dst[(rg + (i << 3)) * D_ + c] = o;
    }
    if (hasE) {
        float4 o = make_float4(ace[0], ace[1], ace[2], ace[3]);
        if (RELU) {
            o.x = fmaxf(o.x, 0.f); o.y = fmaxf(o.y, 0.f);
            o.z = fmaxf(o.z, 0.f); o.w = fmaxf(o.w, 0.f);
        }
        *(float4*)&dst[(rg + 64) * D_ + c] = o;
    }
}

__global__ void __launch_bounds__(NT, 1)
artistbert_kernel(
    const float* __restrict__ X,    const float* __restrict__ mask_in,
    const float* __restrict__ seg_in,
    const float* __restrict__ We,   const float* __restrict__ be,
    const float* __restrict__ Wp,   const float* __restrict__ bp,
    const float* __restrict__ Wsg,  const float* __restrict__ bsg,
    const float* __restrict__ g1,   const float* __restrict__ b1,
    const float* __restrict__ Wq,   const float* __restrict__ bq,
    const float* __restrict__ Wk,   const float* __restrict__ bk,
    const float* __restrict__ Wv,   const float* __restrict__ bv,
    const float* __restrict__ g2,   const float* __restrict__ b2,
    const float* __restrict__ Wd,   const float* __restrict__ bd,
    const float* __restrict__ Wo,   const float* __restrict__ bo,
    float* __restrict__ out)
{
    extern __shared__ float sm[];
    float* xs    = sm + OFF_XS;
    float* qs    = sm + OFF_QS;
    float* ks    = sm + OFF_KS;
    float* vs    = sm + OFF_VS;
    float* wsm   = sm + OFF_W;
    float* sc    = sm + OFF_SC;
    float* red   = sm + OFF_RED;
    float* stats = sm + OFF_ST;
    float* maskv = sm + OFF_MK;
    float* segv  = sm + OFF_SG;
    float* xin   = sm + OFF_XI;

    const int t  = threadIdx.x;
    const int b0 = blockIdx.x * NB;

    // ---------------- stage inputs ----------------
    for (int i = t; i < NB * S_ * V_; i += NT) {
        const int rr = i / V_;          // row 0..67
        const int v  = i - rr * V_;
        xin[rr * 32 + v] = X[(size_t)b0 * S_ * V_ + i];
    }
    for (int i = t; i < ROWS; i += NT)        maskv[i] = mask_in[b0 * S_ + i];
    for (int i = t; i < ROWS * NSEG_; i += NT) segv[i] = seg_in[b0 * S_ * NSEG_ + i];
    // stage We | Wp | Wsg into wsm
    for (int i = t; i < V_ * D_; i += NT)    wsm[i] = We[i];
    for (int i = t; i < S_ * D_; i += NT)    wsm[V_ * D_ + i] = Wp[i];
    for (int i = t; i < NSEG_ * D_; i += NT) wsm[(V_ + S_) * D_ + i] = Wsg[i];
    __syncthreads();

    // ---------------- embedding ----------------
    {
        const int d = t & 127, g = t >> 7;
        const float bias = be[d] + bp[d] + bsg[d];
        for (int rr = g; rr < ROWS; rr += 2) {
            const int s = rr % S_;
            float acc = bias + wsm[(V_ + s) * D_ + d];     // Wp[s][d]
            const float* xr = &xin[rr * 32];
#pragma unroll
            for (int v = 0; v < V_; v++) acc += xr[v] * wsm[v * D_ + d];
            const float* sg = &segv[rr * 4];
#pragma unroll
            for (int n = 0; n < NSEG_; n++) acc += sg[n] * wsm[(V_ + S_ + n) * D_ + d];
            xs[rr * D_ + d] = acc;
        }
    }

    // ---------------- layers ----------------
    for (int l = 0; l < L_; l++) {
        const int wo = l * D_ * D_;
        const int bo_ = l * D_;
        do_gemm<true>(xs, qs, Wq + wo, bq + bo_, wsm);
        do_gemm<true>(xs, ks, Wk + wo, bk + bo_, wsm);
        do_gemm<true>(xs, vs, Wv + wo, bv + bo_, wsm);
        __syncthreads();

        // ----- scores: sc[rr][j] = q[rr] . k[row_j]  (within batch element) -----
        {
            const int warp = t >> 5, lane = t & 31;
            const int sub = lane >> 3;          // which pair in the quad
            const int dd  = (lane & 7) << 4;    // 16-wide d slice
            for (int p4 = warp; p4 < (NB * 289) / 4; p4 += 8) {
                const int p = p4 * 4 + sub;     // p < 1156 always (1156 = 4*289)
                const int e = p / 289;
                const int r = p - e * 289;
                const int s = r / 17;
                const int j = r - s * 17;
                const float* qr = &qs[(e * 17 + s) * D_ + dd];
                const float* kr = &ks[(e * 17 + j) * D_ + dd];
                float part = 0.f;
#pragma unroll
                for (int x = 0; x < 16; x += 4) {
                    const float4 a = *(const float4*)&qr[x];
                    const float4 b = *(const float4*)&kr[x];
                    part += a.x * b.x + a.y * b.y + a.z * b.z + a.w * b.w;
                }
                part += __shfl_xor_sync(0xffffffffu, part, 4);
                part += __shfl_xor_sync(0xffffffffu, part, 2);
                part += __shfl_xor_sync(0xffffffffu, part, 1);
                if ((lane & 7) == 0)
                    sc[(e * 17 + s) * SCP + j] = part;
            }
        }
        __syncthreads();

        // ----- softmax per row -----
        if (t < ROWS) {
            float* r = &sc[t * SCP];
            float m = r[0];
#pragma unroll
            for (int j = 1; j < 17; j++) m = fmaxf(m, r[j]);
            float ex[17], sum = 0.f;
#pragma unroll
            for (int j = 0; j < 17; j++) { ex[j] = __expf(r[j] - m); sum += ex[j]; }
            const float inv = 1.f / sum;
#pragma unroll
            for (int j = 0; j < 17; j++) r[j] = ex[j] * inv;
        }
        __syncthreads();

        // ----- attn + mask + residual, row stats -----
        {
            const int d = t & 127, g = t >> 7;
            const int warp = t >> 5, lane = t & 31;
            for (int rr = g; rr < ROWS; rr += 2) {
                const int ebase = (rr / 17) * 17;
                const float* pr = &sc[rr * SCP];
                const float* vc = &vs[ebase * D_ + d];
                float a = 0.f;
#pragma unroll
                for (int j = 0; j < 17; j++) a += pr[j] * vc[j * D_];
                a *= maskv[rr];
                const float xn = xs[rr * D_ + d] + a;
                xs[rr * D_ + d] = xn;
                float ssum = xn, ssq = xn * xn;
#pragma unroll
                for (int o = 16; o > 0; o >>= 1) {
                    ssum += __shfl_xor_sync(0xffffffffu, ssum, o);
                    ssq  += __shfl_xor_sync(0xffffffffu, ssq, o);
                }
                if (lane == 0) {
                    red[rr * 8 + (warp & 3)]     = ssum;
                    red[rr * 8 + 4 + (warp & 3)] = ssq;
                }
            }
        }
        __syncthreads();
        if (t < ROWS) {
            const float ssum = red[t * 8] + red[t * 8 + 1] + red[t * 8 + 2] + red[t * 8 + 3];
            const float ssq  = red[t * 8 + 4] + red[t * 8 + 5] + red[t * 8 + 6] + red[t * 8 + 7];
            const float mu  = ssum * (1.f / 128.f);
            const float var = ssq * (1.f / 128.f) - mu * mu;
            stats[t * 2]     = mu;
            stats[t * 2 + 1] = rsqrtf(var + EPS_);
        }
        __syncthreads();
        {
            const int d = t & 127, g = t >> 7;
            const float gg = g1[l * D_ + d], bb = b1[l * D_ + d];
            for (int rr = g; rr < ROWS; rr += 2) {
                xs[rr * D_ + d] = (xs[rr * D_ + d] - stats[rr * 2]) * stats[rr * 2 + 1] * gg + bb;
            }
        }

        // ----- dense + residual + LN2 -----
        do_gemm<false>(xs, qs, Wd + wo, bd + bo_, wsm);   // qs reused as xd
        __syncthreads();
        {
            const int d = t & 127, g = t >> 7;
            const int warp = t >> 5, lane = t & 31;
            for (int rr = g; rr < ROWS; rr += 2) {
                const float xn = xs[rr * D_ + d] + qs[rr * D_ + d];
                xs[rr * D_ + d] = xn;
                float ssum = xn, ssq = xn * xn;
#pragma unroll
                for (int o = 16; o > 0; o >>= 1) {
                    ssum += __shfl_xor_sync(0xffffffffu, ssum, o);
                    ssq  += __shfl_xor_sync(0xffffffffu, ssq, o);
                }
                if (lane == 0) {
                    red[rr * 8 + (warp & 3)]     = ssum;
                    red[rr * 8 + 4 + (warp & 3)] = ssq;
                }
            }
        }
        __syncthreads();
        if (t < ROWS) {
            const float ssum = red[t * 8] + red[t * 8 + 1] + red[t * 8 + 2] + red[t * 8 + 3];
            const float ssq  = red[t * 8 + 4] + red[t * 8 + 5] + red[t * 8 + 6] + red[t * 8 + 7];
            const float mu  = ssum * (1.f / 128.f);
            const float var = ssq * (1.f / 128.f) - mu * mu;
            stats[t * 2]     = mu;
            stats[t * 2 + 1] = rsqrtf(var + EPS_);
        }
        __syncthreads();
        {
            const int d = t & 127, g = t >> 7;
            const float gg = g2[l * D_ + d], bb = b2[l * D_ + d];
            for (int rr = g; rr < ROWS; rr += 2) {
                xs[rr * D_ + d] = (xs[rr * D_ + d] - stats[rr * 2]) * stats[rr * 2 + 1] * gg + bb;
            }
        }
    }

    // ---------------- output projection ----------------
    __syncthreads();
    for (int i = t; i < D_ * V_; i += NT) wsm[i] = Wo[i];
    __syncthreads();
    {
        const int v = t & 31, g = t >> 5;
        if (v < V_) {
            const float bov = bo[v];
            for (int rr = g; rr < ROWS; rr += 8) {
                const float* xr = &xs[rr * D_];
                float a = bov;
#pragma unroll 8
                for (int d = 0; d < D_; d++) a += xr[d] * wsm[d * V_ + v];
                out[((size_t)b0 * S_ + rr) * V_ + v] = a;
            }
        }
    }
}

extern "C" void kernel_launch(void* const* d_in, const int* in_sizes, int n_in,
                              void* d_out, int out_size)
{
    (void)in_sizes; (void)n_in; (void)out_size;
    const float* X      = (const float*)d_in[0];
    const float* mask_in= (const float*)d_in[1];
    const float* seg_in = (const float*)d_in[2];
    const float* We     = (const float*)d_in[3];
    const float* be     = (const float*)d_in[4];
    const float* Wp     = (const float*)d_in[5];
    const float* bp     = (const float*)d_in[6];
    const float* Wsg    = (const float*)d_in[7];
    const float* bsg    = (const float*)d_in[8];
    const float* g1     = (const float*)d_in[9];
    const float* b1     = (const float*)d_in[10];
    const float* Wq     = (const float*)d_in[11];
    const float* bq     = (const float*)d_in[12];
    const float* Wk     = (const float*)d_in[13];
    const float* bk     = (const float*)d_in[14];
    const float* Wv     = (const float*)d_in[15];
    const float* bv     = (const float*)d_in[16];
    const float* g2     = (const float*)d_in[17];
    const float* b2     = (const float*)d_in[18];
    const float* Wd     = (const float*)d_in[19];
    const float* bd     = (const float*)d_in[20];
    const float* Wo     = (const float*)d_in[21];
    const float* bo     = (const float*)d_in[22];
    float* out = (float*)d_out;

    cudaFuncSetAttribute(artistbert_kernel,
                         cudaFuncAttributeMaxDynamicSharedMemorySize, SMEM_BYTES);
    artistbert_kernel<<<B_ / NB, NT, SMEM_BYTES>>>(
        X, mask_in, seg_in, We, be, Wp, bp, Wsg, bsg, g1, b1,
        Wq, bq, Wk, bk, Wv, bv, g2, b2, Wd, bd, Wo, bo, out);
}

// round 3
// speedup vs baseline: 1.0004x; 1.0004x over previous
#include <cuda_runtime.h>
#include <cstdint>

#define B_    16384
#define S_    17
#define V_    29
#define D_    128
#define NSEG_ 4
#define L_    6
#define NB    4
#define ROWS  (NB * S_)          // 68
#define NT    256
#define EPS_  1e-5f
#define SCP   20                 // padded score row stride

// ---- shared memory layout (in floats) ----
#define OFF_XS   0
#define OFF_QS   (OFF_XS + ROWS * D_)        // 8704
#define OFF_KS   (OFF_QS + ROWS * D_)
#define OFF_VS   (OFF_KS + ROWS * D_)
#define OFF_W    (OFF_VS + ROWS * D_)        // 34816, 16384 floats
#define OFF_SC   (OFF_W + D_ * D_)           // NB*17*SCP = 1360
#define OFF_RED  (OFF_SC + NB * S_ * SCP)    // ROWS*8
#define OFF_ST   (OFF_RED + ROWS * 8)        // ROWS*2
#define OFF_MK   (OFF_ST + ROWS * 2)         // ROWS
#define OFF_SG   (OFF_MK + ROWS)             // ROWS*4
#define OFF_XI   (OFF_SG + ROWS * 4)         // NB*17*32
#define SMEM_FLOATS (OFF_XI + NB * S_ * 32)
#define SMEM_BYTES  (SMEM_FLOATS * 4)        // 223024 B

// ============================================================
// GEMM: dst[ROWS][128] = act( src[ROWS][128] @ Wg[128][128] + bg )
// Lane owns 4 consecutive output columns, warp owns rows {rg, rg+8, ...}.
// Weights staged into smem (wsm) cooperatively.
// ============================================================
template <bool RELU>
__device__ __forceinline__ void do_gemm(
    const float* __restrict__ src, float* __restrict__ dst,
    const float* __restrict__ Wg, const float* __restrict__ bg,
    float* __restrict__ wsm)
{
    const int t = threadIdx.x;
    __syncthreads();   // prior consumers of wsm / producers of src are done
    {
        const float4* w4 = (const float4*)Wg;
        float4* s4 = (float4*)wsm;
#pragma unroll
        for (int i = 0; i < (D_ * D_ / 4) / NT; i++)   // 16 iters
            s4[t + i * NT] = w4[t + i * NT];
    }
    __syncthreads();

    const int c  = (t & 31) << 2;   // columns c..c+3
    const int rg = t >> 5;          // warp id 0..7 -> rows rg + 8*i
    const bool hasE = (rg < (ROWS - 64));   // rows 64..67 -> warps 0..3

    float acc[8][4];
    float ace[4];
    const float4 bb = *(const float4*)&bg[c];
#pragma unroll
    for (int i = 0; i < 8; i++) {
        acc[i][0] = bb.x; acc[i][1] = bb.y; acc[i][2] = bb.z; acc[i][3] = bb.w;
    }
    ace[0] = bb.x; ace[1] = bb.y; ace[2] = bb.z; ace[3] = bb.w;

#pragma unroll 4
    for (int k = 0; k < D_; k++) {
        const float4 w = *(const float4*)&wsm[k * D_ + c];
#pragma unroll
        for (int i = 0; i < 8; i++) {
            const float xv = src[(rg + (i << 3)) * D_ + k];   // warp-broadcast LDS
            acc[i][0] += xv * w.x; acc[i][1] += xv * w.y;
            acc[i][2] += xv * w.z; acc[i][3] += xv * w.w;
        }
        if (hasE) {
            const float xv = src[(rg + 64) * D_ + k];
            ace[0] += xv * w.x; ace[1] += xv * w.y;
            ace[2] += xv * w.z; ace[3] += xv * w.w;
        }
    }

#pragma unroll
    for (int i = 0; i < 8; i++) {
        float4 o = make_float4(acc[i][0], acc[i][1], acc[i][2], acc[i][3]);
        if (RELU) {
            o.x = fmaxf(o.x, 0.f); o.y = fmaxf(o.y, 0.f);
            o.z = fmaxf(o.z, 0.f); o.w = fmaxf(o.w, 0.f);
        }
        *(float4*)&dst[(rg + (i << 3)) * D_ + c] = o;
    }
    if (hasE) {
        float4 o = make_float4(ace[0], ace[1], ace[2], ace[3]);
        if (RELU) {
            o.x = fmaxf(o.x, 0.f); o.y = fmaxf(o.y, 0.f);
            o.z = fmaxf(o.z, 0.f); o.w = fmaxf(o.w, 0.f);
        }
        *(float4*)&dst[(rg + 64) * D_ + c] = o;
    }
}

__global__ void __launch_bounds__(NT, 1)
artistbert_kernel(
    const float* __restrict__ X,    const float* __restrict__ mask_in,
    const float* __restrict__ seg_in,
    const float* __restrict__ We,   const float* __restrict__ be,
    const float* __restrict__ Wp,   const float* __restrict__ bp,
    const float* __restrict__ Wsg,  const float* __restrict__ bsg,
    const float* __restrict__ g1,   const float* __restrict__ b1,
    const float* __restrict__ Wq,   const float* __restrict__ bq,
    const float* __restrict__ Wk,   const float* __restrict__ bk,
    const float* __restrict__ Wv,   const float* __restrict__ bv,
    const float* __restrict__ g2,   const float* __restrict__ b2,
    const float* __restrict__ Wd,   const float* __restrict__ bd,
    const float* __restrict__ Wo,   const float* __restrict__ bo,
    float* __restrict__ out)
{
    extern __shared__ float sm[];
    float* xs    = sm + OFF_XS;
    float* qs    = sm + OFF_QS;
    float* ks    = sm + OFF_KS;
    float* vs    = sm + OFF_VS;
    float* wsm   = sm + OFF_W;
    float* sc    = sm + OFF_SC;
    float* red   = sm + OFF_RED;
    float* stats = sm + OFF_ST;
    float* maskv = sm + OFF_MK;
    float* segv  = sm + OFF_SG;
    float* xin   = sm + OFF_XI;

    const int t  = threadIdx.x;
    const int b0 = blockIdx.x * NB;

    // ---------------- stage inputs ----------------
    for (int i = t; i < NB * S_ * V_; i += NT) {
        const int rr = i / V_;          // row 0..67
        const int v  = i - rr * V_;
        xin[rr * 32 + v] = X[(size_t)b0 * S_ * V_ + i];
    }
    for (int i = t; i < ROWS; i += NT)        maskv[i] = mask_in[b0 * S_ + i];
    for (int i = t; i < ROWS * NSEG_; i += NT) segv[i] = seg_in[b0 * S_ * NSEG_ + i];
    // stage We | Wp | Wsg into wsm
    for (int i = t; i < V_ * D_; i += NT)    wsm[i] = We[i];
    for (int i = t; i < S_ * D_; i += NT)    wsm[V_ * D_ + i] = Wp[i];
    for (int i = t; i < NSEG_ * D_; i += NT) wsm[(V_ + S_) * D_ + i] = Wsg[i];
    __syncthreads();

    // ---------------- embedding ----------------
    {
        const int d = t & 127, g = t >> 7;
        const float bias = be[d] + bp[d] + bsg[d];
        for (int rr = g; rr < ROWS; rr += 2) {
            const int s = rr % S_;
            float acc = bias + wsm[(V_ + s) * D_ + d];     // Wp[s][d]
            const float* xr = &xin[rr * 32];
#pragma unroll
            for (int v = 0; v < V_; v++) acc += xr[v] * wsm[v * D_ + d];
            const float* sg = &segv[rr * 4];
#pragma unroll
            for (int n = 0; n < NSEG_; n++) acc += sg[n] * wsm[(V_ + S_ + n) * D_ + d];
            xs[rr * D_ + d] = acc;
        }
    }

    // ---------------- layers ----------------
    for (int l = 0; l < L_; l++) {
        const int wo = l * D_ * D_;
        const int bo_ = l * D_;
        do_gemm<true>(xs, qs, Wq + wo, bq + bo_, wsm);
        do_gemm<true>(xs, ks, Wk + wo, bk + bo_, wsm);
        do_gemm<true>(xs, vs, Wv + wo, bv + bo_, wsm);
        __syncthreads();

        // ----- scores: sc[rr][j] = q[rr] . k[row_j]  (within batch element) -----
        {
            const int warp = t >> 5, lane = t & 31;
            const int sub = lane >> 3;          // which pair in the quad
            const int dd  = (lane & 7) << 4;    // 16-wide d slice
            for (int p4 = warp; p4 < (NB * 289) / 4; p4 += 8) {
                const int p = p4 * 4 + sub;     // p < 1156 always (1156 = 4*289)
                const int e = p / 289;
                const int r = p - e * 289;
                const int s = r / 17;
                const int j = r - s * 17;
                const float* qr = &qs[(e * 17 + s) * D_ + dd];
                const float* kr = &ks[(e * 17 + j) * D_ + dd];
                float part = 0.f;
#pragma unroll
                for (int x = 0; x < 16; x += 4) {
                    const float4 a = *(const float4*)&qr[x];
                    const float4 b = *(const float4*)&kr[x];
                    part += a.x * b.x + a.y * b.y + a.z * b.z + a.w * b.w;
                }
                part += __shfl_xor_sync(0xffffffffu, part, 4);
                part += __shfl_xor_sync(0xffffffffu, part, 2);
                part += __shfl_xor_sync(0xffffffffu, part, 1);
                if ((lane & 7) == 0)
                    sc[(e * 17 + s) * SCP + j] = part;
            }
        }
        __syncthreads();

        // ----- softmax per row -----
        if (t < ROWS) {
            float* r = &sc[t * SCP];
            float m = r[0];
#pragma unroll
            for (int j = 1; j < 17; j++) m = fmaxf(m, r[j]);
            float ex[17], sum = 0.f;
#pragma unroll
            for (int j = 0; j < 17; j++) { ex[j] = __expf(r[j] - m); sum += ex[j]; }
            const float inv = 1.f / sum;
#pragma unroll
            for (int j = 0; j < 17; j++) r[j] = ex[j] * inv;
        }
        __syncthreads();

        // ----- attn + mask + residual, row stats -----
        {
            const int d = t & 127, g = t >> 7;
            const int warp = t >> 5, lane = t & 31;
            for (int rr = g; rr < ROWS; rr += 2) {
                const int ebase = (rr / 17) * 17;
                const float* pr = &sc[rr * SCP];
                const float* vc = &vs[ebase * D_ + d];
                float a = 0.f;
#pragma unroll
                for (int j = 0; j < 17; j++) a += pr[j] * vc[j * D_];
                a *= maskv[rr];
                const float xn = xs[rr * D_ + d] + a;
                xs[rr * D_ + d] = xn;
                float ssum = xn, ssq = xn * xn;
#pragma unroll
                for (int o = 16; o > 0; o >>= 1) {
                    ssum += __shfl_xor_sync(0xffffffffu, ssum, o);
                    ssq  += __shfl_xor_sync(0xffffffffu, ssq, o);
                }
                if (lane == 0) {
                    red[rr * 8 + (warp & 3)]     = ssum;
                    red[rr * 8 + 4 + (warp & 3)] = ssq;
                }
            }
        }
        __syncthreads();
        if (t < ROWS) {
            const float ssum = red[t * 8] + red[t * 8 + 1] + red[t * 8 + 2] + red[t * 8 + 3];
            const float ssq  = red[t * 8 + 4] + red[t * 8 + 5] + red[t * 8 + 6] + red[t * 8 + 7];
            const float mu  = ssum * (1.f / 128.f);
            const float var = ssq * (1.f / 128.f) - mu * mu;
            stats[t * 2]     = mu;
            stats[t * 2 + 1] = rsqrtf(var + EPS_);
        }
        __syncthreads();
        {
            const int d = t & 127, g = t >> 7;
            const float gg = g1[l * D_ + d], bb = b1[l * D_ + d];
            for (int rr = g; rr < ROWS; rr += 2) {
                xs[rr * D_ + d] = (xs[rr * D_ + d] - stats[rr * 2]) * stats[rr * 2 + 1] * gg + bb;
            }
        }

        // ----- dense + residual + LN2 -----
        do_gemm<false>(xs, qs, Wd + wo, bd + bo_, wsm);   // qs reused as xd
        __syncthreads();
        {
            const int d = t & 127, g = t >> 7;
            const int warp = t >> 5, lane = t & 31;
            for (int rr = g; rr < ROWS; rr += 2) {
                const float xn = xs[rr * D_ + d] + qs[rr * D_ + d];
                xs[rr * D_ + d] = xn;
                float ssum = xn, ssq = xn * xn;
#pragma unroll
                for (int o = 16; o > 0; o >>= 1) {
                    ssum += __shfl_xor_sync(0xffffffffu, ssum, o);
                    ssq  += __shfl_xor_sync(0xffffffffu, ssq, o);
                }
                if (lane == 0) {
                    red[rr * 8 + (warp & 3)]     = ssum;
                    red[rr * 8 + 4 + (warp & 3)] = ssq;
                }
            }
        }
        __syncthreads();
        if (t < ROWS) {
            const float ssum = red[t * 8] + red[t * 8 + 1] + red[t * 8 + 2] + red[t * 8 + 3];
            const float ssq  = red[t * 8 + 4] + red[t * 8 + 5] + red[t * 8 + 6] + red[t * 8 + 7];
            const float mu  = ssum * (1.f / 128.f);
            const float var = ssq * (1.f / 128.f) - mu * mu;
            stats[t * 2]     = mu;
            stats[t * 2 + 1] = rsqrtf(var + EPS_);
        }
        __syncthreads();
        {
            const int d = t & 127, g = t >> 7;
            const float gg = g2[l * D_ + d], bb = b2[l * D_ + d];
            for (int rr = g; rr < ROWS; rr += 2) {
                xs[rr * D_ + d] = (xs[rr * D_ + d] - stats[rr * 2]) * stats[rr * 2 + 1] * gg + bb;
            }
        }
    }

    // ---------------- output projection ----------------
    __syncthreads();
    for (int i = t; i < D_ * V_; i += NT) wsm[i] = Wo[i];
    __syncthreads();
    {
        const int v = t & 31, g = t >> 5;
        if (v < V_) {
            const float bov = bo[v];
            for (int rr = g; rr < ROWS; rr += 8) {
                const float* xr = &xs[rr * D_];
                float a = bov;
#pragma unroll 8
                for (int d = 0; d < D_; d++) a += xr[d] * wsm[d * V_ + v];
                out[((size_t)b0 * S_ + rr) * V_ + v] = a;
            }
        }
    }
}

extern "C" void kernel_launch(void* const* d_in, const int* in_sizes, int n_in,
                              void* d_out, int out_size)
{
    (void)in_sizes; (void)n_in; (void)out_size;
    const float* X      = (const float*)d_in[0];
    const float* mask_in= (const float*)d_in[1];
    const float* seg_in = (const float*)d_in[2];
    const float* We     = (const float*)d_in[3];
    const float* be     = (const float*)d_in[4];
    const float* Wp     = (const float*)d_in[5];
    const float* bp     = (const float*)d_in[6];
    const float* Wsg    = (const float*)d_in[7];
    const float* bsg    = (const float*)d_in[8];
    const float* g1     = (const float*)d_in[9];
    const float* b1     = (const float*)d_in[10];
    const float* Wq     = (const float*)d_in[11];
    const float* bq     = (const float*)d_in[12];
    const float* Wk     = (const float*)d_in[13];
    const float* bk     = (const float*)d_in[14];
    const float* Wv     = (const float*)d_in[15];
    const float* bv     = (const float*)d_in[16];
    const float* g2     = (const float*)d_in[17];
    const float* b2     = (const float*)d_in[18];
    const float* Wd     = (const float*)d_in[19];
    const float* bd     = (const float*)d_in[20];
    const float* Wo     = (const float*)d_in[21];
    const float* bo     = (const float*)d_in[22];
    float* out = (float*)d_out;

    cudaFuncSetAttribute(artistbert_kernel,
                         cudaFuncAttributeMaxDynamicSharedMemorySize, SMEM_BYTES);
    artistbert_kernel<<<B_ / NB, NT, SMEM_BYTES>>>(
        X, mask_in, seg_in, We, be, Wp, bp, Wsg, bsg, g1, b1,
        Wq, bq, Wk, bk, Wv, bv, g2, b2, Wd, bd, Wo, bo, out);
}